// round 1
// baseline (speedup 1.0000x reference)
#include <cuda_runtime.h>

// ---------------------------------------------------------------------------
// Problem constants (fixed by the reference)
// ---------------------------------------------------------------------------
namespace {
constexpr int NODES  = 50000;
constexpr int EDGES  = 800000;
constexpr int F_IN   = 1280;
constexpr int H      = 256;
constexpr int LAYERS = 4;
constexpr long long NH          = (long long)NODES * H;        // 12,800,000 floats
constexpr long long DENSE_ELEMS = 100LL * 500 * 1024;          // 51,200,000 floats
}

// Scratch: 6 node-feature buffers of [NODES, H] fp32 each (51.2 MB * 6).
__device__ float g_scratch[6ll * NODES * H];

// ---------------------------------------------------------------------------
// GEMM with fused epilogue:
//   C[M, H] = A[M, K] @ W[K, H] (+ bias) (+ addmat) then act
//   act: 0 = none, 1 = relu, 2 = sigmoid
// Tile: BM=128, BN=128, BK=8; 256 threads; 8x8 per thread.
// ---------------------------------------------------------------------------
__global__ void __launch_bounds__(256, 2)
gemm_epi(const float* __restrict__ A, const float* __restrict__ W,
         const float* __restrict__ bias, const float* __restrict__ addmat,
         float* __restrict__ C, int M, int K, int act)
{
    __shared__ float As[8][128];
    __shared__ float Bs[8][128];

    const int tid = threadIdx.x;
    const int tx  = tid & 15;        // 0..15 (column group)
    const int ty  = tid >> 4;        // 0..15 (row group)
    const int rowBase = blockIdx.y * 128;
    const int colBase = blockIdx.x * 128;

    float acc[8][8];
#pragma unroll
    for (int i = 0; i < 8; i++)
#pragma unroll
        for (int j = 0; j < 8; j++) acc[i][j] = 0.f;

    // A-tile load mapping: each thread loads one float4 of A (128 rows x 8 k)
    const int ar = tid >> 1;             // 0..127 row within tile
    const int ak = (tid & 1) * 4;        // 0 or 4 within BK
    // B-tile load mapping: each thread loads one float4 of W (8 k x 128 cols)
    const int bk = tid >> 5;             // 0..7
    const int bc = (tid & 31) * 4;       // 0..124
    const int arow = rowBase + ar;
    const bool arow_ok = (arow < M);
    const float* Aptr = A + (size_t)arow * K + ak;
    const float* Wptr = W + (size_t)bk * H + colBase + bc;

    for (int k0 = 0; k0 < K; k0 += 8) {
        float4 av = make_float4(0.f, 0.f, 0.f, 0.f);
        if (arow_ok) av = *reinterpret_cast<const float4*>(Aptr + k0);
        As[ak + 0][ar] = av.x;
        As[ak + 1][ar] = av.y;
        As[ak + 2][ar] = av.z;
        As[ak + 3][ar] = av.w;

        float4 bv = *reinterpret_cast<const float4*>(Wptr + (size_t)k0 * H);
        *reinterpret_cast<float4*>(&Bs[bk][bc]) = bv;
        __syncthreads();

#pragma unroll
        for (int kk = 0; kk < 8; kk++) {
            float4 a0 = *reinterpret_cast<const float4*>(&As[kk][ty * 8]);
            float4 a1 = *reinterpret_cast<const float4*>(&As[kk][ty * 8 + 4]);
            float4 b0 = *reinterpret_cast<const float4*>(&Bs[kk][tx * 8]);
            float4 b1 = *reinterpret_cast<const float4*>(&Bs[kk][tx * 8 + 4]);
            float ra[8] = {a0.x, a0.y, a0.z, a0.w, a1.x, a1.y, a1.z, a1.w};
            float rb[8] = {b0.x, b0.y, b0.z, b0.w, b1.x, b1.y, b1.z, b1.w};
#pragma unroll
            for (int i = 0; i < 8; i++)
#pragma unroll
                for (int j = 0; j < 8; j++)
                    acc[i][j] = fmaf(ra[i], rb[j], acc[i][j]);
        }
        __syncthreads();
    }

    // Epilogue
    float bvals[8];
#pragma unroll
    for (int j = 0; j < 8; j++)
        bvals[j] = bias ? bias[colBase + tx * 8 + j] : 0.f;

#pragma unroll
    for (int i = 0; i < 8; i++) {
        int grow = rowBase + ty * 8 + i;
        if (grow >= M) break;
        size_t off = (size_t)grow * H + colBase + tx * 8;
        float v[8];
#pragma unroll
        for (int j = 0; j < 8; j++) v[j] = acc[i][j] + bvals[j];
        if (addmat) {
            float4 m0 = *reinterpret_cast<const float4*>(addmat + off);
            float4 m1 = *reinterpret_cast<const float4*>(addmat + off + 4);
            v[0] += m0.x; v[1] += m0.y; v[2] += m0.z; v[3] += m0.w;
            v[4] += m1.x; v[5] += m1.y; v[6] += m1.z; v[7] += m1.w;
        }
        if (act == 1) {
#pragma unroll
            for (int j = 0; j < 8; j++) v[j] = fmaxf(v[j], 0.f);
        } else if (act == 2) {
#pragma unroll
            for (int j = 0; j < 8; j++) v[j] = 1.f / (1.f + __expf(-v[j]));
        }
        *reinterpret_cast<float4*>(C + off)     = make_float4(v[0], v[1], v[2], v[3]);
        *reinterpret_cast<float4*>(C + off + 4) = make_float4(v[4], v[5], v[6], v[7]);
    }
}

// ---------------------------------------------------------------------------
// Edge scatter-add: agg[dst[e], :] += val[src[e], :] via vectorized L2 atomics.
// One thread per (edge, float4-chunk); a warp covers 32 consecutive chunks of
// one edge (half a row) -> coalesced gather + contiguous atomics.
// ---------------------------------------------------------------------------
__global__ void scatter_add_kernel(const float* __restrict__ val,
                                   float* __restrict__ agg,
                                   const int* __restrict__ src,
                                   const int* __restrict__ dst)
{
    long long idx = (long long)blockIdx.x * blockDim.x + threadIdx.x;
    constexpr long long TOTAL = (long long)EDGES * 64;  // 64 float4 per row
    if (idx >= TOTAL) return;
    int e = (int)(idx >> 6);
    int q = (int)(idx & 63);
    int s = __ldg(src + e);
    int d = __ldg(dst + e);
    float4 v = reinterpret_cast<const float4*>(val)[(size_t)s * 64 + q];
    float* p = agg + ((size_t)d * 256 + (size_t)q * 4);
    asm volatile("red.global.add.v4.f32 [%0], {%1, %2, %3, %4};"
                 :: "l"(p), "f"(v.x), "f"(v.y), "f"(v.z), "f"(v.w)
                 : "memory");
}

// ---------------------------------------------------------------------------
// Elementwise helpers
// ---------------------------------------------------------------------------
__global__ void fill4_kernel(float* __restrict__ p, float v, long long n4)
{
    long long i = (long long)blockIdx.x * blockDim.x + threadIdx.x;
    if (i < n4) reinterpret_cast<float4*>(p)[i] = make_float4(v, v, v, v);
}

__global__ void fill_scalar_kernel(float* __restrict__ p, float v, long long n)
{
    long long i = (long long)blockIdx.x * blockDim.x + threadIdx.x;
    if (i < n) p[i] = v;
}

__global__ void mul_kernel(const float* __restrict__ a, const float* __restrict__ b,
                           float* __restrict__ o, long long n4)
{
    long long i = (long long)blockIdx.x * blockDim.x + threadIdx.x;
    if (i >= n4) return;
    float4 x = reinterpret_cast<const float4*>(a)[i];
    float4 y = reinterpret_cast<const float4*>(b)[i];
    reinterpret_cast<float4*>(o)[i] = make_float4(x.x * y.x, x.y * y.y, x.z * y.z, x.w * y.w);
}

// Write layer output x[NODES, 256] into dense output slice
// out[n * (L*H) + layer*H + c]  (to_dense_batch is an identity reshape here)
__global__ void copy_out_kernel(const float* __restrict__ x, float* __restrict__ out, int layer)
{
    long long i = (long long)blockIdx.x * blockDim.x + threadIdx.x;
    constexpr long long N4 = NH / 4;    // 3,200,000
    if (i >= N4) return;
    int n = (int)(i >> 6);
    int q = (int)(i & 63);
    reinterpret_cast<float4*>(out)[(size_t)n * 256 + (size_t)layer * 64 + q] =
        reinterpret_cast<const float4*>(x)[i];
}

// ---------------------------------------------------------------------------
// Launcher
// ---------------------------------------------------------------------------
extern "C" void kernel_launch(void* const* d_in, const int* in_sizes, int n_in,
                              void* d_out, int out_size)
{
    // Input order (metadata): seq, edge_index, esm_token, batch,
    //   lin0_W, lin0_b, wc_W1, wc_b1, wc_W2, wc_b2, wc_W3, wc_b3,
    //   sc_Wn, sc_bn, sc_Wr
    const int*   edge   = (const int*)d_in[1];
    const int*   src    = edge;
    const int*   dst    = edge + EDGES;
    const float* esm    = (const float*)d_in[2];
    const float* lin0_W = (const float*)d_in[4];
    const float* lin0_b = (const float*)d_in[5];
    const float* wc_W1  = (const float*)d_in[6];
    const float* wc_b1  = (const float*)d_in[7];
    const float* wc_W2  = (const float*)d_in[8];
    const float* wc_b2  = (const float*)d_in[9];
    const float* wc_W3  = (const float*)d_in[10];
    const float* wc_b3  = (const float*)d_in[11];
    const float* sc_Wn  = (const float*)d_in[12];
    const float* sc_bn  = (const float*)d_in[13];
    const float* sc_Wr  = (const float*)d_in[14];
    float* out = (float*)d_out;

    float* base = nullptr;
    cudaGetSymbolAddress((void**)&base, g_scratch);
    float* X    = base;                 // current node features
    float* MASK = base + 1 * NH;        // sigmoid mask
    float* WK   = base + 2 * NH;        // work buffer (h_nb / h / xg)
    float* AGG  = base + 3 * NH;        // segment-sum accumulator
    float* TMP  = base + 4 * NH;        // x @ Wr
    float* XM   = base + 5 * NH;        // x * mask (input to next layer)

    const dim3 gemm_grid(2, (NODES + 127) / 128);
    const dim3 gemm_block(256);
    const long long n4 = NH / 4;                         // 3.2M float4
    const int ew_blocks = (int)((n4 + 255) / 256);       // elementwise grids
    const long long sc_total = (long long)EDGES * 64;    // 51.2M threads
    const int sc_blocks = (int)((sc_total + 255) / 256);

    // x = esm @ lin0_W + lin0_b
    gemm_epi<<<gemm_grid, gemm_block>>>(esm, lin0_W, lin0_b, nullptr, X, NODES, F_IN, 0);

    const float* xm = X;   // layer 0: mask is None -> xm = x
    for (int i = 0; i < LAYERS; i++) {
        const float* W1 = wc_W1 + (size_t)i * H * H;
        const float* b1 = wc_b1 + (size_t)i * H;
        const float* W2 = wc_W2 + (size_t)i * H * H;
        const float* b2 = wc_b2 + (size_t)i * H;
        const float* W3 = wc_W3 + (size_t)i * H * H;
        const float* b3 = wc_b3 + (size_t)i * H;
        const float* Wn = sc_Wn + (size_t)i * H * H;
        const float* bn = sc_bn + (size_t)i * H;
        const float* Wr = sc_Wr + (size_t)i * H * H;

        // ---- WeightConv1 ----
        // h_nb = xm @ W2 + b2
        gemm_epi<<<gemm_grid, gemm_block>>>(xm, W2, b2, nullptr, WK, NODES, H, 0);
        // agg = segment_sum(h_nb[src] -> dst)
        fill4_kernel<<<ew_blocks, 256>>>(AGG, 0.f, n4);
        scatter_add_kernel<<<sc_blocks, 256>>>(WK, AGG, src, dst);
        // h = relu(agg + xm @ W1 + b1)
        gemm_epi<<<gemm_grid, gemm_block>>>(xm, W1, b1, AGG, WK, NODES, H, 1);
        // mask = sigmoid(h @ W3 + b3)
        gemm_epi<<<gemm_grid, gemm_block>>>(WK, W3, b3, nullptr, MASK, NODES, H, 2);

        // ---- SparseConv ----
        // xg = x * mask
        mul_kernel<<<ew_blocks, 256>>>(X, MASK, WK, n4);
        // agg2 = segment_sum(xg[src] -> dst)
        fill4_kernel<<<ew_blocks, 256>>>(AGG, 0.f, n4);
        scatter_add_kernel<<<sc_blocks, 256>>>(WK, AGG, src, dst);
        // tmp = x @ Wr
        gemm_epi<<<gemm_grid, gemm_block>>>(X, Wr, nullptr, nullptr, TMP, NODES, H, 0);
        // x = relu(agg2 @ Wn + bn + tmp)
        gemm_epi<<<gemm_grid, gemm_block>>>(AGG, Wn, bn, TMP, X, NODES, H, 1);

        // jumping-knowledge slice i of the dense output (identity reshape)
        copy_out_kernel<<<ew_blocks, 256>>>(X, out, i);

        // xm for next layer = x * mask
        if (i + 1 < LAYERS) {
            mul_kernel<<<ew_blocks, 256>>>(X, MASK, XM, n4);
            xm = XM;
        }
    }

    // node_mask portion (all True -> 1.0f), if the flattened output includes it
    long long tail = (long long)out_size - DENSE_ELEMS;
    if (tail > 0) {
        int tb = (int)((tail + 255) / 256);
        fill_scalar_kernel<<<tb, 256>>>(out + DENSE_ELEMS, 1.0f, tail);
    }
}

// round 4
// speedup vs baseline: 1.4935x; 1.4935x over previous
#include <cuda_runtime.h>
#include <cuda_bf16.h>
#include <cstdint>

// ---------------------------------------------------------------------------
// Problem constants (fixed by the reference)
// ---------------------------------------------------------------------------
namespace {
constexpr int NODES  = 50000;
constexpr int EDGES  = 800000;
constexpr int F_IN   = 1280;
constexpr int H      = 256;
constexpr int LAYERS = 4;
constexpr long long NH          = (long long)NODES * H;        // 12.8M floats
constexpr long long DENSE_ELEMS = 100LL * 500 * 1024;          // 51.2M floats
constexpr long long WT_ELEMS    = 256LL * 1280 + 20LL * 256 * 256;
// ints: cnt[N] + offs[N+1] + cursor[N] + csr[E]
constexpr long long INT_ELEMS   = 3LL * NODES + 2 + EDGES;
}

__device__ float g_scratch[6 * NH + WT_ELEMS + INT_ELEMS];

// ---------------------------------------------------------------------------
// bf16x3 split-precision GEMM on mma.sync (baseline PTX, works on compute_100)
//   C[M,256] = A[M,K](lda) @ Bt[256,K]^T  (+bias) (+addmat[.,256])  act
//   act: 0 none, 1 relu, 2 sigmoid.  C row stride = ldc.
// CTA: 256 threads (8 warps), tile 128x128, warp tile 32x64, K chunks of 32.
// SMEM: double-buffered, hi/lo stored pre-permuted in mma fragment order.
// ---------------------------------------------------------------------------
#define MMA_BF16(cc, a, b) \
    asm volatile("mma.sync.aligned.m16n8k16.row.col.f32.bf16.bf16.f32 " \
                 "{%0,%1,%2,%3}, {%4,%5,%6,%7}, {%8,%9}, {%0,%1,%2,%3};" \
                 : "+f"((cc)[0]), "+f"((cc)[1]), "+f"((cc)[2]), "+f"((cc)[3]) \
                 : "r"((a).x), "r"((a).y), "r"((a).z), "r"((a).w), \
                   "r"((b).x), "r"((b).y))

__global__ void __launch_bounds__(256)
mma_gemm(const float* __restrict__ A, int lda,
         const float* __restrict__ Bt,
         const float* __restrict__ bias, const float* __restrict__ addmat,
         float* __restrict__ C, int ldc, int M, int K, int act)
{
    extern __shared__ uint32_t smu[];   // 2 stages x 8192 u32 (32KB each)

    const int t = threadIdx.x;
    const int lane = t & 31, w = t >> 5;
    const int warp_m = w & 3, warp_n = w >> 2;      // 4 x 2 warp grid
    const int rowBase = blockIdx.x * 128, colBase = blockIdx.y * 128;

    // ---- producer mapping: thread t owns A row pm / Bt row (colBase+pm),
    //      k-halfchunk kst (16 floats) of the 32-k chunk ----
    const int pm  = t >> 1;
    const int kst = t & 1;
    const int grow = rowBase + pm;
    const bool prow_ok = grow < M;
    const float* Ag = A  + (size_t)grow * lda + kst * 16;
    const float* Bg = Bt + (size_t)(colBase + pm) * K + kst * 16;

    // frag-order store bases
    const int mtile = pm >> 4, gidp = pm & 7, rhalf = (pm >> 3) & 1;
    const int ntile = pm >> 3;
    const int baseA = ((kst * 8  + mtile) * 32 + gidp * 4) * 4 + rhalf;
    const int baseB = ((kst * 16 + ntile) * 32 + gidp * 4) * 2;

    float c[2][8][4];
#pragma unroll
    for (int mt = 0; mt < 2; mt++)
#pragma unroll
        for (int nt = 0; nt < 8; nt++)
#pragma unroll
            for (int j = 0; j < 4; j++) c[mt][nt][j] = 0.f;

    float4 ar[4], br[4];

    auto gload = [&](int k0) {
#pragma unroll
        for (int i = 0; i < 4; i++) {
            ar[i] = prow_ok ? *reinterpret_cast<const float4*>(Ag + k0 + i * 4)
                            : make_float4(0.f, 0.f, 0.f, 0.f);
            br[i] = *reinterpret_cast<const float4*>(Bg + k0 + i * 4);
        }
    };
    auto sstore = [&](uint32_t* st) {
        const float* af = reinterpret_cast<const float*>(ar);
        const float* bf = reinterpret_cast<const float*>(br);
        uint32_t *Ah = st, *Al = st + 2048, *Bh = st + 4096, *Bl = st + 6144;
#pragma unroll
        for (int p = 0; p < 8; p++) {
            float f0 = af[2 * p], f1 = af[2 * p + 1];
            __nv_bfloat162 h = __floats2bfloat162_rn(f0, f1);
            __nv_bfloat162 l = __floats2bfloat162_rn(f0 - __bfloat162float(h.x),
                                                     f1 - __bfloat162float(h.y));
            int off = baseA + (p & 3) * 4 + (p >> 2) * 2;
            Ah[off] = *reinterpret_cast<uint32_t*>(&h);
            Al[off] = *reinterpret_cast<uint32_t*>(&l);

            f0 = bf[2 * p]; f1 = bf[2 * p + 1];
            h = __floats2bfloat162_rn(f0, f1);
            l = __floats2bfloat162_rn(f0 - __bfloat162float(h.x),
                                      f1 - __bfloat162float(h.y));
            int offb = baseB + (p & 3) * 2 + (p >> 2);
            Bh[offb] = *reinterpret_cast<uint32_t*>(&h);
            Bl[offb] = *reinterpret_cast<uint32_t*>(&l);
        }
    };

    const int NC = K >> 5;
    gload(0);
    sstore(smu);
    __syncthreads();

    for (int cc = 0; cc < NC; ++cc) {
        if (cc + 1 < NC) gload((cc + 1) << 5);

        const uint32_t* st = smu + (cc & 1) * 8192;
        const uint32_t *Ah = st, *Al = st + 2048, *Bh = st + 4096, *Bl = st + 6144;
#pragma unroll
        for (int ks = 0; ks < 2; ks++) {
            uint4 ah[2], al[2];
#pragma unroll
            for (int mt = 0; mt < 2; mt++) {
                int ia = ((ks * 8 + warp_m * 2 + mt) * 32 + lane) * 4;
                ah[mt] = *reinterpret_cast<const uint4*>(Ah + ia);
                al[mt] = *reinterpret_cast<const uint4*>(Al + ia);
            }
#pragma unroll
            for (int nt = 0; nt < 8; nt++) {
                int ib = ((ks * 16 + warp_n * 8 + nt) * 32 + lane) * 2;
                uint2 bh = *reinterpret_cast<const uint2*>(Bh + ib);
                uint2 bl = *reinterpret_cast<const uint2*>(Bl + ib);
#pragma unroll
                for (int mt = 0; mt < 2; mt++) {
                    MMA_BF16(c[mt][nt], ah[mt], bh);
                    MMA_BF16(c[mt][nt], al[mt], bh);
                    MMA_BF16(c[mt][nt], ah[mt], bl);
                }
            }
        }
        __syncthreads();
        if (cc + 1 < NC) {
            sstore(smu + ((cc + 1) & 1) * 8192);
            __syncthreads();
        }
    }

    // ---- epilogue ----
    const int gid = lane >> 2, tig = lane & 3;
#pragma unroll
    for (int mt = 0; mt < 2; mt++) {
        int r0 = rowBase + warp_m * 32 + mt * 16 + gid;
        int r1 = r0 + 8;
#pragma unroll
        for (int nt = 0; nt < 8; nt++) {
            int col = colBase + warp_n * 64 + nt * 8 + tig * 2;
            float v0 = c[mt][nt][0], v1 = c[mt][nt][1];
            float v2 = c[mt][nt][2], v3 = c[mt][nt][3];
            if (bias) {
                float b0 = bias[col], b1 = bias[col + 1];
                v0 += b0; v1 += b1; v2 += b0; v3 += b1;
            }
            if (addmat) {
                if (r0 < M) {
                    float2 m0 = *reinterpret_cast<const float2*>(addmat + (size_t)r0 * 256 + col);
                    v0 += m0.x; v1 += m0.y;
                }
                if (r1 < M) {
                    float2 m1 = *reinterpret_cast<const float2*>(addmat + (size_t)r1 * 256 + col);
                    v2 += m1.x; v3 += m1.y;
                }
            }
            if (act == 1) {
                v0 = fmaxf(v0, 0.f); v1 = fmaxf(v1, 0.f);
                v2 = fmaxf(v2, 0.f); v3 = fmaxf(v3, 0.f);
            } else if (act == 2) {
                v0 = 1.f / (1.f + __expf(-v0)); v1 = 1.f / (1.f + __expf(-v1));
                v2 = 1.f / (1.f + __expf(-v2)); v3 = 1.f / (1.f + __expf(-v3));
            }
            if (r0 < M) *reinterpret_cast<float2*>(C + (size_t)r0 * ldc + col) = make_float2(v0, v1);
            if (r1 < M) *reinterpret_cast<float2*>(C + (size_t)r1 * ldc + col) = make_float2(v2, v3);
        }
    }
}

// ---------------------------------------------------------------------------
// Weight transpose: Wt[n][k] = W[k][n]
// ---------------------------------------------------------------------------
__global__ void transpose_kernel(const float* __restrict__ W, float* __restrict__ Wt, int K, int N)
{
    __shared__ float t[32][33];
    const int k0 = blockIdx.x * 32, n0 = blockIdx.y * 32;
    const int tx = threadIdx.x, ty = threadIdx.y;
#pragma unroll
    for (int i = ty; i < 32; i += 8) t[i][tx] = W[(size_t)(k0 + i) * N + n0 + tx];
    __syncthreads();
#pragma unroll
    for (int i = ty; i < 32; i += 8) Wt[(size_t)(n0 + i) * K + k0 + tx] = t[tx][i];
}

// ---------------------------------------------------------------------------
// CSR build (by dst) + gather-based segment sum
// ---------------------------------------------------------------------------
__global__ void zero_int_kernel(int* __restrict__ p, int n)
{
    int i = blockIdx.x * 256 + threadIdx.x;
    if (i < n) p[i] = 0;
}

__global__ void hist_kernel(const int* __restrict__ dst, int* __restrict__ cnt)
{
    int e = blockIdx.x * 256 + threadIdx.x;
    if (e < EDGES) atomicAdd(cnt + dst[e], 1);
}

__global__ void scan_kernel(const int* __restrict__ cnt, int* __restrict__ offs)
{
    __shared__ int part[1024];
    const int t = threadIdx.x;
    const int CH = (NODES + 1023) / 1024;
    const int lo = t * CH, hi = min(NODES, lo + CH);
    int s = 0;
    for (int i = lo; i < hi; i++) s += cnt[i];
    part[t] = s;
    __syncthreads();
    for (int d = 1; d < 1024; d <<= 1) {
        int v = (t >= d) ? part[t - d] : 0;
        __syncthreads();
        part[t] += v;
        __syncthreads();
    }
    int run = (t == 0) ? 0 : part[t - 1];
    for (int i = lo; i < hi; i++) { offs[i] = run; run += cnt[i]; }
    if (t == 1023) offs[NODES] = part[1023];
}

__global__ void fill_csr_kernel(const int* __restrict__ src, const int* __restrict__ dst,
                                const int* __restrict__ offs, int* __restrict__ cursor,
                                int* __restrict__ csr)
{
    int e = blockIdx.x * 256 + threadIdx.x;
    if (e < EDGES) {
        int d = dst[e];
        int p = atomicAdd(cursor + d, 1);
        csr[offs[d] + p] = src[e];
    }
}

// agg[n,:] = sum over neighbors s of val[s,:]; 64 threads per node, 4 nodes/CTA
__global__ void __launch_bounds__(256)
gather_agg_kernel(const float* __restrict__ val, const int* __restrict__ offs,
                  const int* __restrict__ csr, float* __restrict__ agg)
{
    int node = blockIdx.x * 4 + (threadIdx.x >> 6);
    int q = threadIdx.x & 63;
    if (node >= NODES) return;
    int e0 = offs[node], e1 = offs[node + 1];
    float4 acc = make_float4(0.f, 0.f, 0.f, 0.f);
    const float4* v4 = reinterpret_cast<const float4*>(val);
    for (int e = e0; e < e1; e++) {
        int s = __ldg(csr + e);
        float4 v = v4[(size_t)s * 64 + q];
        acc.x += v.x; acc.y += v.y; acc.z += v.z; acc.w += v.w;
    }
    reinterpret_cast<float4*>(agg)[(size_t)node * 64 + q] = acc;
}

// ---------------------------------------------------------------------------
// Elementwise helpers
// ---------------------------------------------------------------------------
__global__ void fill_scalar_kernel(float* __restrict__ p, float v, long long n)
{
    long long i = (long long)blockIdx.x * blockDim.x + threadIdx.x;
    if (i < n) p[i] = v;
}

// o[n,256] = X[n*ldx4*4 ..] * Msk[n,256]
__global__ void mul_stride_kernel(const float* __restrict__ X, int ldx4,
                                  const float* __restrict__ Msk, float* __restrict__ o)
{
    long long i = (long long)blockIdx.x * blockDim.x + threadIdx.x;
    constexpr long long N4 = NH / 4;
    if (i >= N4) return;
    int n = (int)(i >> 6);
    int q = (int)(i & 63);
    float4 x = reinterpret_cast<const float4*>(X)[(size_t)n * ldx4 + q];
    float4 m = reinterpret_cast<const float4*>(Msk)[(size_t)n * 64 + q];
    reinterpret_cast<float4*>(o)[(size_t)n * 64 + q] =
        make_float4(x.x * m.x, x.y * m.y, x.z * m.z, x.w * m.w);
}

// ---------------------------------------------------------------------------
// Launcher
// ---------------------------------------------------------------------------
extern "C" void kernel_launch(void* const* d_in, const int* in_sizes, int n_in,
                              void* d_out, int out_size)
{
    const int*   edge   = (const int*)d_in[1];
    const int*   src    = edge;
    const int*   dst    = edge + EDGES;
    const float* esm    = (const float*)d_in[2];
    const float* lin0_W = (const float*)d_in[4];
    const float* lin0_b = (const float*)d_in[5];
    const float* wc_W1  = (const float*)d_in[6];
    const float* wc_b1  = (const float*)d_in[7];
    const float* wc_W2  = (const float*)d_in[8];
    const float* wc_b2  = (const float*)d_in[9];
    const float* wc_W3  = (const float*)d_in[10];
    const float* wc_b3  = (const float*)d_in[11];
    const float* sc_Wn  = (const float*)d_in[12];
    const float* sc_bn  = (const float*)d_in[13];
    const float* sc_Wr  = (const float*)d_in[14];
    float* out = (float*)d_out;

    float* base = nullptr;
    cudaGetSymbolAddress((void**)&base, g_scratch);
    float* X    = base;
    float* MASK = base + 1 * NH;
    float* WK   = base + 2 * NH;
    float* AGG  = base + 3 * NH;
    float* TMP  = base + 4 * NH;
    float* XM   = base + 5 * NH;
    float* WTB  = base + 6 * NH;
    float* L0T  = WTB;                        // [256,1280]
    float* W1T  = L0T + 256LL * 1280;         // [4][256,256] each
    float* W2T  = W1T + 4LL * 65536;
    float* W3T  = W2T + 4LL * 65536;
    float* WnT  = W3T + 4LL * 65536;
    float* WrT  = WnT + 4LL * 65536;
    int*   ibase  = (int*)(WrT + 4LL * 65536);
    int*   cnt    = ibase;
    int*   offs   = cnt + NODES;              // NODES+1
    int*   cursor = offs + NODES + 1;
    int*   csr    = cursor + NODES;           // EDGES

    constexpr int SMEM_BYTES = 64 * 1024;
    cudaFuncSetAttribute(mma_gemm, cudaFuncAttributeMaxDynamicSharedMemorySize, SMEM_BYTES);

    const dim3 gemm_grid((NODES + 127) / 128, 2);   // 391 x 2
    const long long n4 = NH / 4;
    const int ew_blocks = (int)((n4 + 255) / 256);
    const int eb = (EDGES + 255) / 256;
    const int nb = (NODES + 255) / 256;
    const int gather_blocks = (NODES + 3) / 4;
    const dim3 t8(32, 8);

    // ---- CSR build (per replay, deterministic work) ----
    zero_int_kernel<<<nb, 256>>>(cnt, NODES);
    zero_int_kernel<<<nb, 256>>>(cursor, NODES);
    hist_kernel<<<eb, 256>>>(dst, cnt);
    scan_kernel<<<1, 1024>>>(cnt, offs);
    fill_csr_kernel<<<eb, 256>>>(src, dst, offs, cursor, csr);

    // ---- transpose all weights ----
    transpose_kernel<<<dim3(F_IN / 32, H / 32), t8>>>(lin0_W, L0T, F_IN, H);
    for (int i = 0; i < LAYERS; i++) {
        size_t o = (size_t)i * 65536;
        transpose_kernel<<<dim3(8, 8), t8>>>(wc_W1 + o, W1T + o, H, H);
        transpose_kernel<<<dim3(8, 8), t8>>>(wc_W2 + o, W2T + o, H, H);
        transpose_kernel<<<dim3(8, 8), t8>>>(wc_W3 + o, W3T + o, H, H);
        transpose_kernel<<<dim3(8, 8), t8>>>(sc_Wn + o, WnT + o, H, H);
        transpose_kernel<<<dim3(8, 8), t8>>>(sc_Wr + o, WrT + o, H, H);
    }

    // x = esm @ lin0_W + b
    mma_gemm<<<gemm_grid, 256, SMEM_BYTES>>>(esm, F_IN, L0T, lin0_b, nullptr, X, H, NODES, F_IN, 0);

    const float* xm = X; int ldxm = H;
    const float* xc = X; int ldxc = H;
    for (int i = 0; i < LAYERS; i++) {
        size_t o = (size_t)i * 65536, ob = (size_t)i * H;
        // ---- WeightConv1 ----
        mma_gemm<<<gemm_grid, 256, SMEM_BYTES>>>(xm, ldxm, W2T + o, wc_b2 + ob, nullptr,
                                                 WK, H, NODES, H, 0);
        gather_agg_kernel<<<gather_blocks, 256>>>(WK, offs, csr, AGG);
        mma_gemm<<<gemm_grid, 256, SMEM_BYTES>>>(xm, ldxm, W1T + o, wc_b1 + ob, AGG,
                                                 WK, H, NODES, H, 1);
        mma_gemm<<<gemm_grid, 256, SMEM_BYTES>>>(WK, H, W3T + o, wc_b3 + ob, nullptr,
                                                 MASK, H, NODES, H, 2);
        // ---- SparseConv ----
        mul_stride_kernel<<<ew_blocks, 256>>>(xc, ldxc / 4, MASK, WK);
        gather_agg_kernel<<<gather_blocks, 256>>>(WK, offs, csr, AGG);
        mma_gemm<<<gemm_grid, 256, SMEM_BYTES>>>(xc, ldxc, WrT + o, nullptr, nullptr,
                                                 TMP, H, NODES, H, 0);
        float* xnew = out + (size_t)i * H;      // JK slice, row stride 1024
        mma_gemm<<<gemm_grid, 256, SMEM_BYTES>>>(AGG, H, WnT + o, sc_bn + ob, TMP,
                                                 xnew, LAYERS * H, NODES, H, 1);
        xc = xnew; ldxc = LAYERS * H;
        if (i + 1 < LAYERS) {
            mul_stride_kernel<<<ew_blocks, 256>>>(xc, ldxc / 4, MASK, XM);
            xm = XM; ldxm = H;
        }
    }

    // node_mask tail (all True -> 1.0f)
    long long tail = (long long)out_size - DENSE_ELEMS;
    if (tail > 0) {
        int tb = (int)((tail + 255) / 256);
        fill_scalar_kernel<<<tb, 256>>>(out + DENSE_ELEMS, 1.0f, tail);
    }
}